// round 14
// baseline (speedup 1.0000x reference)
#include <cuda_runtime.h>
#include <cuda_bf16.h>
#include <cstdint>

// Problem constants (fixed by the reference generator).
#define NN   4096      // nodes
#define BB   2048      // batch
#define LL   128       // latent
#define KK   16        // max fan-in
#define DW   145       // 1 + LL + KK  (weights row length)
#define GKK  129       // 1 + LL       (GEMM K dim)

#define NE      14     // batch elements per CTA (147 CTAs -> one wave)
#define STRIDE  4097   // per-element smem stride: bank = (el + p) mod 32
#define PAD     40     // meta/pre pad rows (max refill overrun = +32)

#define STATE_F (NE * STRIDE)                 // 57,358 floats of chain state
#define SMEM_CHAIN_BYTES ((STATE_F + 4) * 4)  // 229,448 B

// ---------------------------------------------------------------------------
// Scratch (__device__ globals zero-initialized at load; all writes idempotent
// across graph replays; padded rows never written -> overrun reads zeros).
// ---------------------------------------------------------------------------
__device__ float        g_pre[(NN + PAD) * BB];   // pre[i*BB+b] = bias + z.wz
__device__ unsigned int g_meta[(NN + PAD) * 32];  // 16 parent idx + 16 weight bits
__device__ int          g_pmax[NN + 8];           // max live parent index (-1 none)
__device__ int          g_lvl[NN + 8];            // level boundaries (ends), ~390 used

// ---------------------------------------------------------------------------
// Kernel 0: probe (shifts ncu's -s 5 capture slot toward chain_kernel).
// ---------------------------------------------------------------------------
__global__ void probe_kernel()
{
    if (threadIdx.x == 0) g_pre[(size_t)(NN + PAD) * BB - 1] = 0.0f;
}

// ---------------------------------------------------------------------------
// Kernel 1: pack per-node metadata (128B line: 16 parents + 16 pre-masked
// weights) and pmax[i] = max over live parents (mask!=0), else -1.
// ---------------------------------------------------------------------------
__global__ void pack_meta_kernel(const float* __restrict__ w,
                                 const int*   __restrict__ par,
                                 const float* __restrict__ mask)
{
    const int wid = threadIdx.x >> 5;
    const int k   = threadIdx.x & 31;
    const int i   = blockIdx.x * 8 + wid;
    if (i >= NN) return;

    int p_eff = -1;
    if (k < 16) {
        int p = par[i * KK + k];
        g_meta[i * 32 + k]      = (unsigned)p;
        g_meta[i * 32 + 16 + k] = __float_as_uint(w[i * DW + (1 + LL) + k]);
        if (mask[i * KK + k] != 0.0f) p_eff = p;
    }
    int pm = __reduce_max_sync(0xffffffffu, p_eff);
    if (k == 0) g_pmax[i] = pm;
}

// ---------------------------------------------------------------------------
// Kernel 1b: greedy level boundaries (single warp; pmax staged in smem).
// lvl[l] = end of level l: first j >= a with pmax[j] >= a (or NN).
// Guaranteed progress: pmax[a] < a always (parents precede).
// ---------------------------------------------------------------------------
__global__ void levels_kernel()
{
    __shared__ int sp[NN];
    const int lane = threadIdx.x;                  // 32 threads
    for (int j = lane; j < NN; j += 32) sp[j] = g_pmax[j];
    __syncwarp();

    int a = 0, l = 0;
    while (a < NN) {
        int c = NN;
        for (int base = a; base < NN; base += 32) {
            int idx = base + lane;
            int v = (idx < NN) ? sp[idx] : 0x7fffffff;
            unsigned bal = __ballot_sync(0xffffffffu, v >= a);
            if (bal) { c = base + __ffs(bal) - 1; break; }
        }
        if (c <= a) c = a + 1;                     // safety (unreachable)
        if (lane == 0) g_lvl[l] = c;
        l++;
        a = c;
    }
    if (lane == 0) g_lvl[l] = NN;                  // terminator padding
}

// ---------------------------------------------------------------------------
// Kernel 2: pre[i][b] = sum_{k=0}^{128} w[i][k] * base[b][k],  base=[1, z].
// ---------------------------------------------------------------------------
#define G_PAD 68
__global__ void gemm_pre_kernel(const float* __restrict__ z,
                                const float* __restrict__ w)
{
    extern __shared__ float smg[];
    float* As = smg;
    float* Zs = smg + GKK * G_PAD;

    const int i0 = blockIdx.y * 64;
    const int b0 = blockIdx.x * 64;
    const int tid = threadIdx.x;

    for (int idx = tid; idx < 64 * GKK; idx += 256) {
        int r = idx / GKK, k = idx - r * GKK;
        As[k * G_PAD + r] = w[(i0 + r) * DW + k];
    }
    for (int idx = tid; idx < 64 * GKK; idx += 256) {
        int c = idx / GKK, k = idx - c * GKK;
        Zs[k * G_PAD + c] = (k == 0) ? 1.0f : z[(b0 + c) * LL + (k - 1)];
    }
    __syncthreads();

    const int tx = tid & 15;
    const int ty = tid >> 4;
    const int ri = ty * 4, ci = tx * 4;

    float acc[4][4];
#pragma unroll
    for (int r = 0; r < 4; r++)
#pragma unroll
        for (int c = 0; c < 4; c++) acc[r][c] = 0.0f;

#pragma unroll 3
    for (int k = 0; k < GKK; k++) {
        float4 a  = *reinterpret_cast<const float4*>(&As[k * G_PAD + ri]);
        float4 zc = *reinterpret_cast<const float4*>(&Zs[k * G_PAD + ci]);
        float av[4] = {a.x, a.y, a.z, a.w};
        float zv[4] = {zc.x, zc.y, zc.z, zc.w};
#pragma unroll
        for (int r = 0; r < 4; r++)
#pragma unroll
            for (int c = 0; c < 4; c++)
                acc[r][c] = fmaf(av[r], zv[c], acc[r][c]);
    }

#pragma unroll
    for (int r = 0; r < 4; r++) {
        float4 o = make_float4(acc[r][0], acc[r][1], acc[r][2], acc[r][3]);
        *reinterpret_cast<float4*>(&g_pre[(size_t)(i0 + ri + r) * BB + b0 + ci]) = o;
    }
}

// ---------------------------------------------------------------------------
// Kernel 3: level-scheduled chain with a STATIC schedule and continuous
// prefetch. Warp w owns the fixed node stream w, w+16, w+32, ... with
// depth-2 register prefetch of meta/pre flowing ACROSS level boundaries.
// Per level l (precomputed end c = g_lvl[l]): each warp drains its nodes
// below c from prefetched registers, then one __syncthreads(). Boundaries
// are register-prefetched one level ahead. No scans, no polling, no serial
// segment; barriers uniform; ~390 levels total.
// ---------------------------------------------------------------------------
__global__ void __launch_bounds__(512, 1)
chain_kernel(float* __restrict__ out)
{
    extern __shared__ float sm[];
    const int tid  = threadIdx.x;
    const int warp = tid >> 5;
    const int lane = tid & 31;

    for (int j = tid; j < STATE_F; j += 512) sm[j] = 0.0f;

    const int  elc = lane < 14 ? lane : 13;        // lanes 14-31 mirror el 13
    const bool so  = (lane < 14);
    int b = blockIdx.x * NE + elc; if (b >= BB) b = BB - 1;
    float* __restrict__ u = sm + elc * STRIDE;

    const int4*   mp = reinterpret_cast<const int4*>(g_meta);
    const float4* mw = reinterpret_cast<const float4*>(g_meta);

    // Depth-2 register prefetch: slot d holds node n where (n>>4)&1 == d.
    int4   P[2][4];
    float4 W[2][4];
    float  pre[2];
#pragma unroll
    for (int d = 0; d < 2; d++) {
        const int n = warp + d * 16;
#pragma unroll
        for (int q = 0; q < 4; q++) P[d][q] = __ldg(mp + (size_t)n * 8 + q);
#pragma unroll
        for (int q = 0; q < 4; q++) W[d][q] = __ldg(mw + (size_t)n * 8 + 4 + q);
        pre[d] = __ldg(g_pre + (size_t)n * BB + b);
    }

    int n = warp;                                  // next node this warp owns
    int c_cur = __ldg(g_lvl);                      // end of level 0
    __syncthreads();

#pragma unroll 1
    for (int l = 0;; l++) {
        const int c_nxt = __ldg(g_lvl + l + 1);    // prefetch next boundary

        // Drain this warp's nodes below c_cur (usually 0-2 iterations).
#pragma unroll 1
        while (n < c_cur) {
            const int d = (n >> 4) & 1;

            // gathers + dot (all parents committed in earlier levels)
            int4 p0 = P[d][0], p1 = P[d][1], p2 = P[d][2], p3 = P[d][3];
            float g0  = u[p0.x], g1  = u[p0.y], g2  = u[p0.z], g3  = u[p0.w];
            float g4  = u[p1.x], g5  = u[p1.y], g6  = u[p1.z], g7  = u[p1.w];
            float g8  = u[p2.x], g9  = u[p2.y], g10 = u[p2.z], g11 = u[p2.w];
            float g12 = u[p3.x], g13 = u[p3.y], g14 = u[p3.z], g15 = u[p3.w];

            float a0 = fmaf(g0,  W[d][0].x, pre[d]);
            float a1 = g1  * W[d][0].y;
            float a2 = g2  * W[d][0].z;
            float a3 = g3  * W[d][0].w;
            a0 = fmaf(g4,  W[d][1].x, a0);
            a1 = fmaf(g5,  W[d][1].y, a1);
            a2 = fmaf(g6,  W[d][1].z, a2);
            a3 = fmaf(g7,  W[d][1].w, a3);
            a0 = fmaf(g8,  W[d][2].x, a0);
            a1 = fmaf(g9,  W[d][2].y, a1);
            a2 = fmaf(g10, W[d][2].z, a2);
            a3 = fmaf(g11, W[d][2].w, a3);
            a0 = fmaf(g12, W[d][3].x, a0);
            a1 = fmaf(g13, W[d][3].y, a1);
            a2 = fmaf(g14, W[d][3].z, a2);
            a3 = fmaf(g15, W[d][3].w, a3);
            float s = (a0 + a1) + (a2 + a3);

            float e, r;
            asm("ex2.approx.f32 %0, %1;" : "=f"(e) : "f"(s * 2.885390082f));
            asm("rcp.approx.f32 %0, %1;" : "=f"(r) : "f"(e + 1.0f));
            float t = fmaf(-2.0f, r, 1.0f);
            if (so) u[n] = t;

            // refill slot d with node n+32 (padded rows -> zeros)
            {
                const int nf = n + 32;
#pragma unroll
                for (int q = 0; q < 4; q++) P[d][q] = __ldg(mp + (size_t)nf * 8 + q);
#pragma unroll
                for (int q = 0; q < 4; q++) W[d][q] = __ldg(mw + (size_t)nf * 8 + 4 + q);
                pre[d] = __ldg(g_pre + (size_t)nf * BB + b);
            }
            n += 16;
        }

        __syncthreads();                           // level committed
        if (c_cur >= NN) break;
        c_cur = c_nxt;
    }

    // Cooperative coalesced dump: SMEM -> out[b*NN + i].
    for (int e = 0; e < NE; e++) {
        const int bo = blockIdx.x * NE + e;
        if (bo >= BB) break;
        const float* __restrict__ us = sm + e * STRIDE;
        for (int j = tid; j < NN; j += 512)
            out[(size_t)bo * NN + j] = us[j];
    }
}

// ---------------------------------------------------------------------------
// Launch. Inputs: z f32[2048,128], weights f32[4096,145],
// parent_mask f32[4096,16], parents i32[4096,16]. Output: f32[2048, 4096].
// ---------------------------------------------------------------------------
extern "C" void kernel_launch(void* const* d_in, const int* in_sizes, int n_in,
                              void* d_out, int out_size)
{
    const float* z       = (const float*)d_in[0];
    const float* weights = (const float*)d_in[1];
    const float* pmask   = (const float*)d_in[2];
    const int*   parents = (const int*)d_in[3];
    float*       out     = (float*)d_out;

    const int gemm_smem  = 2 * GKK * G_PAD * (int)sizeof(float);   // 70,176 B
    const int chain_smem = SMEM_CHAIN_BYTES;                        // 229,448 B

    cudaFuncSetAttribute(gemm_pre_kernel,
                         cudaFuncAttributeMaxDynamicSharedMemorySize, gemm_smem);
    cudaFuncSetAttribute(chain_kernel,
                         cudaFuncAttributeMaxDynamicSharedMemorySize, chain_smem);

    probe_kernel<<<1, 32>>>();

    pack_meta_kernel<<<(NN + 7) / 8, 256>>>(weights, parents, pmask);
    levels_kernel<<<1, 32>>>();

    dim3 ggrid(BB / 64, NN / 64);
    gemm_pre_kernel<<<ggrid, 256, gemm_smem>>>(z, weights);

    const int nblocks = (BB + NE - 1) / NE;   // 147
    chain_kernel<<<nblocks, 512, chain_smem>>>(out);
}

// round 15
// speedup vs baseline: 1.1888x; 1.1888x over previous
#include <cuda_runtime.h>
#include <cuda_bf16.h>
#include <cstdint>

// Problem constants (fixed by the reference generator).
#define NN   4096      // nodes
#define BB   2048      // batch
#define LL   128       // latent
#define KK   16        // max fan-in
#define DW   145       // 1 + LL + KK  (weights row length)
#define GKK  129       // 1 + LL       (GEMM K dim)

#define NE      14     // batch elements per CTA (147 CTAs -> one wave)
#define STRIDE  4097   // per-element smem stride: bank = (el + p) mod 32
#define PAD     40     // meta/pre pad rows (max prefetch overrun ~ +16)

#define CH      4      // nodes per chunk
#define NCH     1024   // chunks (4*1024 = 4096 exactly)
#define SCALE   2.885390082f   // 2*log2(e): tanh via ex2 without FMUL

#define STATE_F (NE * STRIDE)        // 57,358 floats of chain state
#define META_F  (STATE_F + 2)        // 3 bufs x 128 floats (4 nodes x 128B)
#define PREW_F  (META_F + 3 * 128)   // 3 bufs x 64 floats (4 nodes x [14 pre, w1, 0])
#define SMEM_CHAIN_BYTES ((PREW_F + 3 * 64 + 4) * 4)   // 231,760 B <= 232,448

// ---------------------------------------------------------------------------
// Scratch (__device__ globals zero-initialized at load; rows >= NN never
// written -> clamped/overrun reads return zeros; all writes idempotent).
// ---------------------------------------------------------------------------
__device__ float        g_pre[(NN + PAD) * BB];   // pre[i*BB+b], PRE-SCALED by 2log2e
__device__ unsigned int g_meta[(NN + PAD) * 32];  // 16 parent idx + 16 scaled-w bits
__device__ float        g_w1[NN + PAD];           // scaled sum of w over parent==i-1

// ---------------------------------------------------------------------------
// Kernel 0: probe (shifts ncu's -s 5 capture slot toward chain_kernel).
// ---------------------------------------------------------------------------
__global__ void probe_kernel()
{
    if (threadIdx.x == 0) g_pre[(size_t)(NN + PAD) * BB - 1] = 0.0f;
}

// ---------------------------------------------------------------------------
// Kernel 1: pack per-node metadata (128B line: 16 parents + 16 SCALED
// weights) and w1[i] = scaled sum of weights whose live parent == i-1.
// ---------------------------------------------------------------------------
__global__ void pack_meta_kernel(const float* __restrict__ w,
                                 const int*   __restrict__ par,
                                 const float* __restrict__ mask)
{
    const int wid = threadIdx.x >> 5;
    const int k   = threadIdx.x & 31;
    const int i   = blockIdx.x * 8 + wid;
    if (i >= NN) return;

    float pw = 0.0f;
    if (k < 16) {
        int   p  = par[i * KK + k];
        float wk = w[i * DW + (1 + LL) + k] * SCALE;   // pre-masked, pre-scaled
        g_meta[i * 32 + k]      = (unsigned)p;
        g_meta[i * 32 + 16 + k] = __float_as_uint(wk);
        if (mask[i * KK + k] != 0.0f && p == i - 1) pw = wk;
    }
    #pragma unroll
    for (int off = 8; off > 0; off >>= 1)
        pw += __shfl_down_sync(0xffffffffu, pw, off);
    if (k == 0) g_w1[i] = pw;
}

// ---------------------------------------------------------------------------
// Kernel 2: pre[i][b] = SCALE * sum_k w[i][k]*base[b][k],  base=[1, z].
// ---------------------------------------------------------------------------
#define G_PAD 68
__global__ void gemm_pre_kernel(const float* __restrict__ z,
                                const float* __restrict__ w)
{
    extern __shared__ float smg[];
    float* As = smg;
    float* Zs = smg + GKK * G_PAD;

    const int i0 = blockIdx.y * 64;
    const int b0 = blockIdx.x * 64;
    const int tid = threadIdx.x;

    for (int idx = tid; idx < 64 * GKK; idx += 256) {
        int r = idx / GKK, k = idx - r * GKK;
        As[k * G_PAD + r] = w[(i0 + r) * DW + k] * SCALE;
    }
    for (int idx = tid; idx < 64 * GKK; idx += 256) {
        int c = idx / GKK, k = idx - c * GKK;
        Zs[k * G_PAD + c] = (k == 0) ? 1.0f : z[(b0 + c) * LL + (k - 1)];
    }
    __syncthreads();

    const int tx = tid & 15;
    const int ty = tid >> 4;
    const int ri = ty * 4, ci = tx * 4;

    float acc[4][4];
#pragma unroll
    for (int r = 0; r < 4; r++)
#pragma unroll
        for (int c = 0; c < 4; c++) acc[r][c] = 0.0f;

#pragma unroll 3
    for (int k = 0; k < GKK; k++) {
        float4 a  = *reinterpret_cast<const float4*>(&As[k * G_PAD + ri]);
        float4 zc = *reinterpret_cast<const float4*>(&Zs[k * G_PAD + ci]);
        float av[4] = {a.x, a.y, a.z, a.w};
        float zv[4] = {zc.x, zc.y, zc.z, zc.w};
#pragma unroll
        for (int r = 0; r < 4; r++)
#pragma unroll
            for (int c = 0; c < 4; c++)
                acc[r][c] = fmaf(av[r], zv[c], acc[r][c]);
    }

#pragma unroll
    for (int r = 0; r < 4; r++) {
        float4 o = make_float4(acc[r][0], acc[r][1], acc[r][2], acc[r][3]);
        *reinterpret_cast<float4*>(&g_pre[(size_t)(i0 + ri + r) * BB + b0 + ci]) = o;
    }
}

// ---------------------------------------------------------------------------
// Producer helpers (warp 1): register-staged chunk loads / smem stores.
// Per chunk (4 nodes): 32 float4 meta + 64 floats prew ([14 pre, w1, 0] x4).
// ---------------------------------------------------------------------------
__device__ __forceinline__ float prew_load(int node, int slot, int b0)
{
    if (node > NN + PAD - 1) node = NN + PAD - 1;
    if (slot < 14) {
        int b = b0 + slot; if (b >= BB) b = BB - 1;
        return __ldg(&g_pre[(size_t)node * BB + b]);
    }
    if (slot == 14) return __ldg(&g_w1[node]);
    return 0.0f;
}

__device__ __forceinline__ void prod_ldg4(int c, int b0, int lane,
                                          float4& m, float& p0, float& p1)
{
    const int base = c * CH;
    int node = base + (lane >> 3);
    if (node > NN + PAD - 1) node = NN + PAD - 1;
    m  = __ldg(reinterpret_cast<const float4*>(g_meta) + (size_t)node * 8 + (lane & 7));
    p0 = prew_load(base + (lane >> 4),       lane & 15, b0);
    p1 = prew_load(base + (lane >> 4) + 2,   lane & 15, b0);
}

__device__ __forceinline__ void prod_sts4(float* sm, int c, int lane,
                                          float4 m, float p0, float p1)
{
    const int buf = c % 3;
    reinterpret_cast<float4*>(sm + META_F)[buf * 32 + lane] = m;
    sm[PREW_F + buf * 64 + lane]      = p0;
    sm[PREW_F + buf * 64 + lane + 32] = p1;
}

// ---------------------------------------------------------------------------
// Kernel 3: serial chain, 64 threads. Warp 0 = consumer: every ring read
// (P, W, pre, w1) is consumed exactly one iteration after it issues
// (parity-double-buffered registers, chunk unrolled x4) -> no exposed LDS
// latency. Warp 1 = producer, register-pipelined 2 phases deep (R9).
// Stale-read trick: gathers for node m+1 issue at the TOP of iter m
// (before u[m] store); the parent==m slot reads 0 and is patched next
// iteration via s += t_prev * w1. tanh = 1 - 2/(ex2(s_scaled)+1).
// ---------------------------------------------------------------------------
__global__ void __launch_bounds__(64, 1)
chain_kernel(float* __restrict__ out)
{
    extern __shared__ float sm[];
    const int tid  = threadIdx.x;
    const int warp = tid >> 5;
    const int lane = tid & 31;
    const int b0   = blockIdx.x * NE;

    for (int j = tid; j < STATE_F; j += 64) sm[j] = 0.0f;
    __syncthreads();

    // Producer prologue: fill buffers 0..2, preload reg set B (= chunk 3).
    float4 mA, mB; float pA0 = 0.f, pA1 = 0.f, pB0 = 0.f, pB1 = 0.f;
    if (warp == 1) {
        for (int cc = 0; cc < 3; cc++) {
            prod_ldg4(cc, b0, lane, mA, pA0, pA1);
            prod_sts4(sm, cc, lane, mA, pA0, pA1);
        }
        prod_ldg4(3, b0, lane, mB, pB0, pB1);
    }
    __syncthreads();

    if (warp == 0) {
        // ------------------------------ consumer ---------------------------
        const int  elc = lane < 14 ? lane : 13;    // lanes 14-31 mirror el 13
        const bool so  = (lane < 14);
        float* __restrict__ u = sm + elc * STRIDE;

        const float4* metaR = reinterpret_cast<const float4*>(sm + META_F);

        int4   Pr[2][4];
        float4 Wr[2][4];
        float  preR[2], w1R[2];
        float  gA[16], gB[16];                      // gA = parity0, gB = parity1
        float  t1 = 0.0f;

        // Prologue: node 1's parents (parity1), node 0's W/pre/w1 (parity0).
        {
            const float4* s1 = metaR + 0 * 32 + 1 * 8;   // buf0 slot1
#pragma unroll
            for (int q = 0; q < 4; q++) {
                float4 v = s1[q];
                Pr[1][q] = make_int4(__float_as_int(v.x), __float_as_int(v.y),
                                     __float_as_int(v.z), __float_as_int(v.w));
            }
            const float4* s0 = metaR + 0 * 32 + 0 * 8;   // buf0 slot0
#pragma unroll
            for (int q = 0; q < 4; q++) Wr[0][q] = s0[4 + q];
            preR[0] = sm[PREW_F + 0 * 64 + 0 * 16 + elc];
            w1R[0]  = sm[PREW_F + 0 * 64 + 0 * 16 + 14];
        }
#pragma unroll
        for (int q = 0; q < 16; q++) gA[q] = 0.0f;  // node 0 gathers

// BODY(J): PA=J&1 parity of node m=c*4+J; PB=(J+1)&1.
//   GCUR/GNX = gather buffers (node m / node m+1).
//   P[m+2] from (PBUF, PSLOT) -> Pr[PA]; W/prew[m+1] from (WBUF, WSLOT).
#define BODY(J, GCUR, GNX, PBUF, PSLOT, WBUF, WSLOT)                          \
        {                                                                     \
            const int PA = (J) & 1, PB = ((J) + 1) & 1;                       \
            /* 1. gathers for node m+1 (before u[m] store; stale -> w1) */    \
            {                                                                 \
                int4 q0 = Pr[PB][0], q1 = Pr[PB][1];                          \
                int4 q2 = Pr[PB][2], q3 = Pr[PB][3];                          \
                GNX[0]  = u[q0.x]; GNX[1]  = u[q0.y];                         \
                GNX[2]  = u[q0.z]; GNX[3]  = u[q0.w];                         \
                GNX[4]  = u[q1.x]; GNX[5]  = u[q1.y];                         \
                GNX[6]  = u[q1.z]; GNX[7]  = u[q1.w];                         \
                GNX[8]  = u[q2.x]; GNX[9]  = u[q2.y];                         \
                GNX[10] = u[q2.z]; GNX[11] = u[q2.w];                         \
                GNX[12] = u[q3.x]; GNX[13] = u[q3.y];                         \
                GNX[14] = u[q3.z]; GNX[15] = u[q3.w];                         \
            }                                                                 \
            /* 2. dot for node m from last iter's gathers + this parity W */  \
            float a0 = fmaf(GCUR[0],  Wr[PA][0].x, preR[PA]);                 \
            float a1 = GCUR[1]  * Wr[PA][0].y;                                \
            float a2 = GCUR[2]  * Wr[PA][0].z;                                \
            float a3 = GCUR[3]  * Wr[PA][0].w;                                \
            a0 = fmaf(GCUR[4],  Wr[PA][1].x, a0);                             \
            a1 = fmaf(GCUR[5],  Wr[PA][1].y, a1);                             \
            a2 = fmaf(GCUR[6],  Wr[PA][1].z, a2);                             \
            a3 = fmaf(GCUR[7],  Wr[PA][1].w, a3);                             \
            a0 = fmaf(GCUR[8],  Wr[PA][2].x, a0);                             \
            a1 = fmaf(GCUR[9],  Wr[PA][2].y, a1);                             \
            a2 = fmaf(GCUR[10], Wr[PA][2].z, a2);                             \
            a3 = fmaf(GCUR[11], Wr[PA][2].w, a3);                             \
            a0 = fmaf(GCUR[12], Wr[PA][3].x, a0);                             \
            a1 = fmaf(GCUR[13], Wr[PA][3].y, a1);                             \
            a2 = fmaf(GCUR[14], Wr[PA][3].z, a2);                             \
            a3 = fmaf(GCUR[15], Wr[PA][3].w, a3);                             \
            float s = (a0 + a1) + (a2 + a3);                                  \
            /* 3. refills: P[m+2] -> Pr[PA]; W/prew[m+1] -> parity PB */      \
            {                                                                 \
                const float4* ps = metaR + (PBUF) * 32 + (PSLOT) * 8;         \
                _Pragma("unroll")                                             \
                for (int q = 0; q < 4; q++) {                                 \
                    float4 v = ps[q];                                         \
                    Pr[PA][q] = make_int4(__float_as_int(v.x),                \
                                          __float_as_int(v.y),                \
                                          __float_as_int(v.z),                \
                                          __float_as_int(v.w));               \
                }                                                             \
                const float4* wsrc = metaR + (WBUF) * 32 + (WSLOT) * 8;       \
                _Pragma("unroll")                                             \
                for (int q = 0; q < 4; q++) Wr[PB][q] = wsrc[4 + q];          \
                preR[PB] = sm[PREW_F + (WBUF) * 64 + (WSLOT) * 16 + elc];     \
                w1R[PB]  = sm[PREW_F + (WBUF) * 64 + (WSLOT) * 16 + 14];      \
            }                                                                 \
            /* 4. patch + tanh + commit */                                    \
            s = fmaf(t1, w1R[PA], s);                                         \
            float e, r;                                                       \
            asm("ex2.approx.f32 %0, %1;" : "=f"(e) : "f"(s));                 \
            asm("rcp.approx.f32 %0, %1;" : "=f"(r) : "f"(e + 1.0f));          \
            float t = fmaf(-2.0f, r, 1.0f);                                   \
            if (so) u[m + (J)] = t;                                           \
            t1 = t;                                                           \
        }

#pragma unroll 1
        for (int c = 0; c < NCH; c++) {
            const int cur = c % 3;
            const int nxt = (cur == 2) ? 0 : cur + 1;
            const int m   = c << 2;
            BODY(0, gA, gB, cur, 2, cur, 1)
            BODY(1, gB, gA, cur, 3, cur, 2)
            BODY(2, gA, gB, nxt, 0, cur, 3)
            BODY(3, gB, gA, nxt, 1, nxt, 0)
            __syncthreads();                       // phase boundary
        }
#undef BODY
    } else {
        // ------------------------------ producer ---------------------------
#pragma unroll 1
        for (int c = 0; c < NCH; c += 2) {
            if (c > 0) prod_sts4(sm, c + 2, lane, mA, pA0, pA1);
            prod_ldg4(c + 4, b0, lane, mA, pA0, pA1);
            __syncthreads();
            prod_sts4(sm, c + 3, lane, mB, pB0, pB1);
            prod_ldg4(c + 5, b0, lane, mB, pB0, pB1);
            __syncthreads();
        }
    }
    __syncthreads();

    // Coalesced dump: 4 scalar LDS + 1 STG.128 per 16B.
    for (int e = 0; e < NE; e++) {
        const int b = blockIdx.x * NE + e;
        if (b >= BB) break;
        const float* __restrict__ us = sm + e * STRIDE;
        float4* __restrict__ o4 = reinterpret_cast<float4*>(out + (size_t)b * NN);
        for (int j = tid; j < NN / 4; j += 64) {
            float4 v = make_float4(us[j * 4], us[j * 4 + 1],
                                   us[j * 4 + 2], us[j * 4 + 3]);
            o4[j] = v;
        }
    }
}

// ---------------------------------------------------------------------------
// Launch. Inputs: z f32[2048,128], weights f32[4096,145],
// parent_mask f32[4096,16], parents i32[4096,16]. Output: f32[2048, 4096].
// ---------------------------------------------------------------------------
extern "C" void kernel_launch(void* const* d_in, const int* in_sizes, int n_in,
                              void* d_out, int out_size)
{
    const float* z       = (const float*)d_in[0];
    const float* weights = (const float*)d_in[1];
    const float* pmask   = (const float*)d_in[2];
    const int*   parents = (const int*)d_in[3];
    float*       out     = (float*)d_out;

    const int gemm_smem  = 2 * GKK * G_PAD * (int)sizeof(float);   // 70,176 B
    const int chain_smem = SMEM_CHAIN_BYTES;                        // 231,760 B

    cudaFuncSetAttribute(gemm_pre_kernel,
                         cudaFuncAttributeMaxDynamicSharedMemorySize, gemm_smem);
    cudaFuncSetAttribute(chain_kernel,
                         cudaFuncAttributeMaxDynamicSharedMemorySize, chain_smem);

    probe_kernel<<<1, 32>>>();

    pack_meta_kernel<<<(NN + 7) / 8, 256>>>(weights, parents, pmask);

    dim3 ggrid(BB / 64, NN / 64);
    gemm_pre_kernel<<<ggrid, 256, gemm_smem>>>(z, weights);

    const int nblocks = (BB + NE - 1) / NE;   // 147
    chain_kernel<<<nblocks, 64, chain_smem>>>(out);
}